// round 9
// baseline (speedup 1.0000x reference)
#include <cuda_runtime.h>
#include <cooperative_groups.h>

namespace cg = cooperative_groups;

// FPS, torch_geometric semantics. 16 clouds x 16384 -> 4096 samples/cloud.
// 4-CTA cluster per cloud (64 CTAs), 4096 points per CTA, min-dists in regs.
// Cross-CTA winner exchange via DSMEM records + mbarrier release/acquire
// handshake (no cluster.sync in the loop).
// Bit-exact arithmetic (validated R6/R8): d = (dx*dx+dy*dy)+dz*dz, RN, no FMA
// contraction, sub = add of negated. argmax = first occurrence (lowest index).
// Output: float32 values of global indices.

#define N_CLOUDS 16
#define PTS      16384
#define M_SAMP   4096
#define THREADS  512
#define CL       4
#define QTR      4096    // points per CTA
#define PAIRS    4       // 8 points per thread = 4 f32x2 pairs

__device__ __forceinline__ unsigned long long pack2(float lo, float hi) {
    unsigned long long r;
    asm("mov.b64 %0, {%1, %2};" : "=l"(r) : "f"(lo), "f"(hi));
    return r;
}
__device__ __forceinline__ void unpack2(unsigned long long v, float& lo, float& hi) {
    asm("mov.b64 {%0, %1}, %2;" : "=f"(lo), "=f"(hi) : "l"(v));
}
__device__ __forceinline__ unsigned long long add2(unsigned long long a, unsigned long long b) {
    unsigned long long r;
    asm("add.rn.f32x2 %0, %1, %2;" : "=l"(r) : "l"(a), "l"(b));
    return r;
}
__device__ __forceinline__ unsigned long long mul2(unsigned long long a, unsigned long long b) {
    unsigned long long r;
    asm("mul.rn.f32x2 %0, %1, %2;" : "=l"(r) : "l"(a), "l"(b));
    return r;
}
__device__ __forceinline__ unsigned int smem_u32(const void* p) {
    unsigned int a;
    asm("{ .reg .u64 t; cvta.to.shared.u64 t, %1; cvt.u32.u64 %0, t; }"
        : "=r"(a) : "l"(p));
    return a;
}
__device__ __forceinline__ unsigned int mapa_u32(unsigned int local_addr, unsigned int peer) {
    unsigned int r;
    asm("mapa.shared::cluster.u32 %0, %1, %2;" : "=r"(r) : "r"(local_addr), "r"(peer));
    return r;
}

struct __align__(8) Slot { unsigned long long key; float x, y, z; };

__global__ __launch_bounds__(THREADS, 1) __cluster_dims__(CL, 1, 1)
void fps_kernel(const float* __restrict__ pos, float* __restrict__ out)
{
    __shared__ unsigned long long skeys[16];   // per-warp reduced keys
    __shared__ Slot slots[2][CL];              // [parity][rank] exchange records
    __shared__ unsigned long long mbar;        // 3 arrives per phase (peers)

    cg::cluster_group cluster = cg::this_cluster();
    const unsigned rank = cluster.block_rank();          // 0..3
    const int b    = blockIdx.x >> 2;                    // cloud id
    const int base = (int)rank * QTR;                    // cloud-local CTA offset

    const int t    = threadIdx.x;
    const int lane = t & 31;
    const int wid  = t >> 5;
    const float* p = pos + (size_t)b * PTS * 3;

    const unsigned int mbar_a  = smem_u32(&mbar);
    const unsigned int slots_a = smem_u32(&slots[0][0]);

    if (t == 0) {
        asm volatile("mbarrier.init.shared.b64 [%0], %1;" :: "r"(mbar_a), "r"(CL - 1) : "memory");
    }

    // This thread's 8 points: cloud-local index g = base + t + (k<<9), k=0..7.
    unsigned long long CX[PAIRS], CY[PAIRS], CZ[PAIRS];
    float d[2 * PAIRS];
    const float INF = __int_as_float(0x7f800000);

#pragma unroll
    for (int pr = 0; pr < PAIRS; ++pr) {
        int g0 = base + t + ((2 * pr)     << 9);
        int g1 = base + t + ((2 * pr + 1) << 9);
        float x0 = p[3 * g0 + 0], y0 = p[3 * g0 + 1], z0 = p[3 * g0 + 2];
        float x1 = p[3 * g1 + 0], y1 = p[3 * g1 + 1], z1 = p[3 * g1 + 2];
        CX[pr] = pack2(x0, x1);
        CY[pr] = pack2(y0, y1);
        CZ[pr] = pack2(z0, z1);
        d[2 * pr]     = INF;
        d[2 * pr + 1] = INF;
    }

    // First pick: cloud-local index 0 (L1-broadcast load by all threads).
    float sx = p[0], sy = p[1], sz = p[2];
    if (t == 0 && rank == 0) out[b * M_SAMP] = (float)(b * PTS);

    // All mbarriers initialized before any arrive can target them.
    cluster.sync();

    for (int i = 1; i < M_SAMP; ++i) {
        const unsigned long long nx2 = pack2(-sx, -sx);
        const unsigned long long ny2 = pack2(-sy, -sy);
        const unsigned long long nz2 = pack2(-sz, -sz);

        float best = 0.0f;
        int jj = 0;

#pragma unroll
        for (int pr = 0; pr < PAIRS; ++pr) {
            unsigned long long dx = add2(CX[pr], nx2);       // exact sub
            unsigned long long dy = add2(CY[pr], ny2);
            unsigned long long dz = add2(CZ[pr], nz2);
            unsigned long long s  = add2(add2(mul2(dx, dx), mul2(dy, dy)), mul2(dz, dz));
            float lo, hi;
            unpack2(s, lo, hi);
            {
                float nd = fminf(d[2 * pr], lo);
                d[2 * pr] = nd;
                bool c = nd > best; best = c ? nd : best; jj = c ? 2 * pr : jj;
            }
            {
                float nd = fminf(d[2 * pr + 1], hi);
                d[2 * pr + 1] = nd;
                bool c = nd > best; best = c ? nd : best; jj = c ? 2 * pr + 1 : jj;
            }
        }

        // u64 key: high = dist bits, low = ~cloud_local_idx (lowest-index ties).
        const unsigned int gidx = (unsigned int)(base + t) + ((unsigned int)jj << 9);
        const unsigned long long mykey =
            ((unsigned long long)__float_as_uint(best) << 32) |
            (unsigned long long)(0xFFFFFFFFu - gidx);

        unsigned long long key = mykey;
#pragma unroll
        for (int off = 16; off > 0; off >>= 1) {
            unsigned long long o = __shfl_xor_sync(0xFFFFFFFFu, key, off);
            if (o > key) key = o;
        }
        if (lane == 0) skeys[wid] = key;
        __syncthreads();                                   // (A)

        unsigned long long kbest = skeys[0];
#pragma unroll
        for (int w = 1; w < 16; ++w) {
            unsigned long long o = skeys[w];
            if (o > kbest) kbest = o;
        }

        const int par = i & 1;

        // Unique owner (pre-reduction key == CTA max): publish record to own
        // slot and to all peers' slots, then arrive (release) on peers' mbars.
        if (mykey == kbest) {
            const int prw = jj >> 1;
            const int hw  = jj & 1;
            float wx = 0.f, wy = 0.f, wz = 0.f;
#pragma unroll
            for (int pr = 0; pr < PAIRS; ++pr) {
                if (pr == prw) {
                    float l0, h0, l1, h1, l2, h2;
                    unpack2(CX[pr], l0, h0);
                    unpack2(CY[pr], l1, h1);
                    unpack2(CZ[pr], l2, h2);
                    wx = hw ? h0 : l0;
                    wy = hw ? h1 : l1;
                    wz = hw ? h2 : l2;
                }
            }
            // Local record (visible to local threads after barrier (B)).
            slots[par][rank].key = kbest;
            slots[par][rank].x = wx;
            slots[par][rank].y = wy;
            slots[par][rank].z = wz;

            const unsigned int my_slot = slots_a + (unsigned)(par * CL + rank) * sizeof(Slot);
#pragma unroll
            for (unsigned pr_ = 1; pr_ < CL; ++pr_) {
                const unsigned peer = (rank + pr_) & (CL - 1);
                const unsigned int rs = mapa_u32(my_slot, peer);
                asm volatile("st.shared::cluster.u64 [%0], %1;" :: "r"(rs), "l"(kbest) : "memory");
                asm volatile("st.shared::cluster.f32 [%0+8],  %1;" :: "r"(rs), "f"(wx) : "memory");
                asm volatile("st.shared::cluster.f32 [%0+12], %1;" :: "r"(rs), "f"(wy) : "memory");
                asm volatile("st.shared::cluster.f32 [%0+16], %1;" :: "r"(rs), "f"(wz) : "memory");
            }
#pragma unroll
            for (unsigned pr_ = 1; pr_ < CL; ++pr_) {
                const unsigned peer = (rank + pr_) & (CL - 1);
                const unsigned int rm = mapa_u32(mbar_a, peer);
                asm volatile("mbarrier.arrive.release.cluster.shared::cluster.b64 _, [%0];"
                             :: "r"(rm) : "memory");
            }
        }

        __syncthreads();                                   // (B) local slot visible

        // Wait for all 3 peers' records (phase parity = (i-1)&1).
        {
            const unsigned int parity = (unsigned)((i - 1) & 1);
            asm volatile(
                "{\n\t.reg .pred P;\n"
                "W%=:\n\tmbarrier.try_wait.parity.acquire.cluster.shared::cta.b64 P, [%0], %1, 0x989680;\n"
                "\t@!P bra W%=;\n\t}"
                :: "r"(mbar_a), "r"(parity) : "memory");
        }

        // Combine 4 records (keys globally unique).
        const Slot* sp = slots[par];
        unsigned long long gk = sp[0].key;
        int wi = 0;
#pragma unroll
        for (int w = 1; w < CL; ++w) {
            unsigned long long o = sp[w].key;
            if (o > gk) { gk = o; wi = w; }
        }
        sx = sp[wi].x; sy = sp[wi].y; sz = sp[wi].z;

        if (t == 0 && rank == 0) {
            const unsigned int gw = 0xFFFFFFFFu - (unsigned int)gk;
            out[b * M_SAMP + i] = (float)(b * PTS + (int)gw);
        }
    }
}

extern "C" void kernel_launch(void* const* d_in, const int* in_sizes, int n_in,
                              void* d_out, int out_size)
{
    // Resolve pos BY SIZE (786432 floats), robust to input ordering.
    const float* pos = nullptr;
    for (int i = 0; i < n_in; ++i) {
        if (in_sizes[i] == N_CLOUDS * PTS * 3) { pos = (const float*)d_in[i]; break; }
    }
    if (!pos) pos = (const float*)d_in[0];

    float* out = (float*)d_out;   // [N_CLOUDS*M_SAMP] float32 index values

    fps_kernel<<<N_CLOUDS * CL, THREADS>>>(pos, out);
}